// round 1
// baseline (speedup 1.0000x reference)
#include <cuda_runtime.h>
#include <cuda_bf16.h>

// MetaPolicyTransformer: N = B*T independent sequences, S=5, D=4, H=2 (hd=2),
// FF=16, L=3 layers. One thread per sequence; all weights staged in smem.

#define D_ 4
#define S_ 5
#define FF_ 16
#define L_ 3
#define BLK 256

__global__ __launch_bounds__(BLK) void mpt_kernel(
    const float* __restrict__ xin,   // (N, 4, 4) = (N, M, D)
    const float* __restrict__ cls,   // (4,)
    const float* __restrict__ Wqkv,  // (3, 12, 4)
    const float* __restrict__ bqkv,  // (3, 12)
    const float* __restrict__ Wo,    // (3, 4, 4)
    const float* __restrict__ bo,    // (3, 4)
    const float* __restrict__ W1,    // (3, 16, 4)
    const float* __restrict__ b1,    // (3, 16)
    const float* __restrict__ W2,    // (3, 4, 16)
    const float* __restrict__ b2,    // (3, 4)
    float* __restrict__ out_fg,      // (N, 4)
    float* __restrict__ out_sub,     // (N, 16)
    int N)
{
    __shared__ float sWqkv[L_ * 48];
    __shared__ float sbqkv[L_ * 12];
    __shared__ float sWo[L_ * 16];
    __shared__ float sbo[L_ * 4];
    __shared__ float sW1[L_ * 64];
    __shared__ float sb1[L_ * 16];
    __shared__ float sW2[L_ * 64];
    __shared__ float sb2[L_ * 4];
    __shared__ float scls[4];

    const int t = threadIdx.x;
    for (int i = t; i < L_ * 48; i += BLK) sWqkv[i] = Wqkv[i];
    for (int i = t; i < L_ * 12; i += BLK) sbqkv[i] = bqkv[i];
    for (int i = t; i < L_ * 16; i += BLK) sWo[i]   = Wo[i];
    for (int i = t; i < L_ * 4;  i += BLK) sbo[i]   = bo[i];
    for (int i = t; i < L_ * 64; i += BLK) sW1[i]   = W1[i];
    for (int i = t; i < L_ * 16; i += BLK) sb1[i]   = b1[i];
    for (int i = t; i < L_ * 64; i += BLK) sW2[i]   = W2[i];
    for (int i = t; i < L_ * 4;  i += BLK) sb2[i]   = b2[i];
    if (t < 4) scls[t] = cls[t];
    __syncthreads();

    const int n = blockIdx.x * BLK + t;
    if (n >= N) return;

    // Positional encoding constants: pe[s] = [sin(s), cos(s), sin(0.01 s), cos(0.01 s)]
    const float pe[S_][D_] = {
        { 0.0f,                 1.0f,                0.0f,                 1.0f               },
        { 0.84147098480789651f, 0.54030230586813977f, 0.0099998333341666645f, 0.99995000041666528f },
        { 0.90929742682568170f, -0.41614683654714241f, 0.019998666693333084f, 0.99980000666657776f },
        { 0.14112000805986722f, -0.98999249660044542f, 0.029995500337493652f, 0.99955003374899023f },
        { -0.75680249530792820f, -0.65364362086361194f, 0.039989334186634161f, 0.99920010665856564f }
    };

    float x[S_][D_];
    // Row 0: cls token + pe[0]
    #pragma unroll
    for (int d = 0; d < D_; d++) x[0][d] = scls[d] + pe[0][d];
    // Rows 1..4: regional states + pe
    const float4* xp = reinterpret_cast<const float4*>(xin + (size_t)n * 16);
    #pragma unroll
    for (int s = 1; s < S_; s++) {
        float4 r = xp[s - 1];
        x[s][0] = r.x + pe[s][0];
        x[s][1] = r.y + pe[s][1];
        x[s][2] = r.z + pe[s][2];
        x[s][3] = r.w + pe[s][3];
    }

    #pragma unroll 1
    for (int l = 0; l < L_; l++) {
        const float* wq  = sWqkv + l * 48;
        const float* bq  = sbqkv + l * 12;
        const float* wo  = sWo   + l * 16;
        const float* bov = sbo   + l * 4;
        const float* w1  = sW1   + l * 64;
        const float* b1v = sb1   + l * 16;
        const float* w2  = sW2   + l * 64;
        const float* b2v = sb2   + l * 4;

        // QKV projection
        float q[S_][D_], kk[S_][D_], v[S_][D_];
        #pragma unroll
        for (int s = 0; s < S_; s++) {
            #pragma unroll
            for (int o = 0; o < D_; o++) {
                float aq = bq[o], ak = bq[4 + o], av = bq[8 + o];
                #pragma unroll
                for (int c = 0; c < D_; c++) {
                    aq = fmaf(x[s][c], wq[o * 4 + c], aq);
                    ak = fmaf(x[s][c], wq[(4 + o) * 4 + c], ak);
                    av = fmaf(x[s][c], wq[(8 + o) * 4 + c], av);
                }
                q[s][o] = aq; kk[s][o] = ak; v[s][o] = av;
            }
        }

        // Attention (H=2 heads, hd=2), scale = 1/sqrt(2)
        const float scale = 0.70710678118654752f;
        float attn_o[S_][D_];
        #pragma unroll
        for (int h = 0; h < 2; h++) {
            #pragma unroll
            for (int i = 0; i < S_; i++) {
                float sc[S_];
                float mx = -1e30f;
                #pragma unroll
                for (int j = 0; j < S_; j++) {
                    sc[j] = (q[i][2*h] * kk[j][2*h] + q[i][2*h+1] * kk[j][2*h+1]) * scale;
                    mx = fmaxf(mx, sc[j]);
                }
                float sum = 0.0f;
                #pragma unroll
                for (int j = 0; j < S_; j++) { sc[j] = __expf(sc[j] - mx); sum += sc[j]; }
                float inv = __frcp_rn(sum);
                float o0 = 0.0f, o1 = 0.0f;
                #pragma unroll
                for (int j = 0; j < S_; j++) {
                    float a = sc[j] * inv;
                    o0 = fmaf(a, v[j][2*h], o0);
                    o1 = fmaf(a, v[j][2*h+1], o1);
                }
                attn_o[i][2*h]   = o0;
                attn_o[i][2*h+1] = o1;
            }
        }

        // Output projection + residual
        #pragma unroll
        for (int s = 0; s < S_; s++) {
            float nx[D_];
            #pragma unroll
            for (int d = 0; d < D_; d++) {
                float a = bov[d];
                #pragma unroll
                for (int c = 0; c < D_; c++) a = fmaf(attn_o[s][c], wo[d * 4 + c], a);
                nx[d] = x[s][d] + a;
            }
            #pragma unroll
            for (int d = 0; d < D_; d++) x[s][d] = nx[d];
        }

        // Feed-forward + residual
        #pragma unroll
        for (int s = 0; s < S_; s++) {
            float h1[FF_];
            #pragma unroll
            for (int f = 0; f < FF_; f++) {
                float a = b1v[f];
                #pragma unroll
                for (int c = 0; c < D_; c++) a = fmaf(x[s][c], w1[f * 4 + c], a);
                h1[f] = fmaxf(a, 0.0f);
            }
            #pragma unroll
            for (int d = 0; d < D_; d++) {
                float a = b2v[d];
                #pragma unroll
                for (int f = 0; f < FF_; f++) a = fmaf(h1[f], w2[d * 16 + f], a);
                x[s][d] += a;
            }
        }
    }

    // Outputs: F_g = row 0, subregion = rows 1..4
    float4* fg = reinterpret_cast<float4*>(out_fg + (size_t)n * 4);
    *fg = make_float4(x[0][0], x[0][1], x[0][2], x[0][3]);
    float4* sub = reinterpret_cast<float4*>(out_sub + (size_t)n * 16);
    #pragma unroll
    for (int s = 1; s < S_; s++)
        sub[s - 1] = make_float4(x[s][0], x[s][1], x[s][2], x[s][3]);
}

extern "C" void kernel_launch(void* const* d_in, const int* in_sizes, int n_in,
                              void* d_out, int out_size) {
    const float* xin  = (const float*)d_in[0];
    const float* cls  = (const float*)d_in[1];
    const float* Wqkv = (const float*)d_in[2];
    const float* bqkv = (const float*)d_in[3];
    const float* Wo   = (const float*)d_in[4];
    const float* bo   = (const float*)d_in[5];
    const float* W1   = (const float*)d_in[6];
    const float* b1   = (const float*)d_in[7];
    const float* W2   = (const float*)d_in[8];
    const float* b2   = (const float*)d_in[9];

    const int N = in_sizes[0] / 16;          // 1,310,720 sequences
    float* out_fg  = (float*)d_out;          // (N, 4)
    float* out_sub = (float*)d_out + (size_t)N * 4;  // (N, 16)

    const int grid = (N + BLK - 1) / BLK;
    mpt_kernel<<<grid, BLK>>>(xin, cls, Wqkv, bqkv, Wo, bo, W1, b1, W2, b2,
                              out_fg, out_sub, N);
}